// round 13
// baseline (speedup 1.0000x reference)
#include <cuda_runtime.h>
#include <math.h>

// Fused DTCWT scattering layer, round 13: warp-autonomous pipelines, zero __syncthreads.
//  - each warp owns 32 pair-columns; private smem ring of 80-float row segments
//    (8 halo | 64 data | 8 halo), staged by the warp's own cp.async ops
//  - synchronization: cp.async.wait_group + __syncwarp only (no CTA barriers at all)
//  - edge warps (0,7) stage reflected halos via 4B cp.async on lanes 24..31
//  - packed f32x2 filters with symmetric-tap sharing; compile-time ring indices
// x: (32,3,512,512) f32 -> out: (32,21,256,256) f32

#define TILE_OY 16
#define NTHREADS 256
#define NWARP 8
#define SEGW 80                    // floats per row segment: 8 halo | 64 | 8 halo
#define NSLOT 16
#define SMEM_FLOATS (NWARP*NSLOT*SEGW)         // 10240
#define SMEM_BYTES (SMEM_FLOATS*4)             // 40960

// h0: [-0.05, 0.25, 0.6, 0.25, -0.05]  (symmetric)
#define G0 (-0.05f)
#define G1 (0.25f)
#define G2 (0.6f)
// h1: [-0.0107143, 0.0535714, 0.2607143, -0.6071429, ...] (symmetric)
#define H0 (-0.0107143f)
#define H1 (0.0535714f)
#define H2 (0.2607143f)
#define H3 (-0.6071429f)

typedef unsigned long long u64;

__device__ __forceinline__ u64 pk(float lo, float hi) {
    u64 r; asm("mov.b64 %0,{%1,%2};" : "=l"(r) : "f"(lo), "f"(hi)); return r;
}
__device__ __forceinline__ void upk(u64 v, float& a, float& b) {
    asm("mov.b64 {%0,%1},%2;" : "=f"(a), "=f"(b) : "l"(v));
}
__device__ __forceinline__ u64 add2(u64 a, u64 b) {
    u64 r; asm("add.rn.f32x2 %0,%1,%2;" : "=l"(r) : "l"(a), "l"(b)); return r;
}
__device__ __forceinline__ u64 mul2(u64 a, u64 b) {
    u64 r; asm("mul.rn.f32x2 %0,%1,%2;" : "=l"(r) : "l"(a), "l"(b)); return r;
}
__device__ __forceinline__ u64 fma2(u64 a, u64 b, u64 c) {
    u64 r; asm("fma.rn.f32x2 %0,%1,%2,%3;" : "=l"(r) : "l"(a), "l"(b), "l"(c)); return r;
}

__device__ __forceinline__ int refl(int i) {
    i = (i < 0) ? (-i - 1) : i;
    return (i > 511) ? (1023 - i) : i;
}
__device__ __forceinline__ float sqrt_approx(float v) {
    float r; asm("sqrt.approx.f32 %0, %1;" : "=f"(r) : "f"(v)); return r;
}
// band value = sqrt((re^2+im^2)/2 + 1e-4) - 0.01  (1/sqrt2 folded in)
__device__ __forceinline__ float bandmag(float re, float im) {
    return sqrt_approx(0.5f * fmaf(re, re, fmaf(im, im, 2e-4f))) - 0.01f;
}

__device__ __forceinline__ void commit_group() {
    asm volatile("cp.async.commit_group;\n" ::: "memory");
}
__device__ __forceinline__ void wait_all() {
    asm volatile("cp.async.wait_group 0;\n" ::: "memory");
}

// Stage nr rows (window indices m0..m0+nr-1) into this warp's ring.
// Per row: lanes cmin..cmax copy one 16B chunk; on edge warps lanes 24..31 copy
// one reflected 4B halo value. All async; caller does commit/wait/syncwarp.
__device__ __forceinline__ void stage_rows(const float* __restrict__ xin, float* seg,
                                           int lane, int wi, int R, int m0, int nr) {
    const int cmin = (wi == 0) ? 2 : 0;
    const int cmax = (wi == 7) ? 17 : 19;
    const bool body = (lane >= cmin) && (lane <= cmax);
    const bool halo = ((wi == 0) || (wi == 7)) && (lane >= 24);
    const int colbase = 64*wi - 8 + 4*lane;            // body source col
    // halo: k = lane-24 (0..7)
    const int k = lane - 24;
    const int hsrc = (wi == 0) ? (7 - k) : (511 - k);  // reflected source col
    const int hdst = (wi == 0) ? k : (72 + k);         // segment float offset

    for (int j = 0; j < nr; ++j) {
        const int m  = m0 + j;
        const int gy = refl(R + m);
        const float* rowp = xin + (size_t)gy * 512;
        float* slotp = seg + (m & (NSLOT-1)) * SEGW;
        if (body) {
            unsigned dst = (unsigned)__cvta_generic_to_shared(slotp + 4*lane);
            asm volatile("cp.async.cg.shared.global [%0], [%1], 16;\n"
                         :: "r"(dst), "l"(rowp + colbase) : "memory");
        }
        if (halo) {
            unsigned dst = (unsigned)__cvta_generic_to_shared(slotp + hdst);
            asm volatile("cp.async.ca.shared.global [%0], [%1], 4;\n"
                         :: "r"(dst), "l"(rowp + hsrc) : "memory");
        }
    }
}

// branch-free horizontal filters: p points at this thread's center pair (w3,w4)
__device__ __forceinline__ void hfilt_row(const float* __restrict__ p,
                                          u64 g0p, u64 g1p, u64 g2p,
                                          u64 h0p, u64 h1p, u64 h2p, u64 h3p,
                                          u64& loxy, u64& hizw) {
    const u64 PA = *(const u64*)(p - 4);   // (w-1,w0)
    const u64 PB = *(const u64*)(p - 2);   // (w1,w2)
    const u64 PC = *(const u64*)(p    );   // (w3,w4)
    const u64 PD = *(const u64*)(p + 2);   // (w5,w6)
    const u64 PE = *(const u64*)(p + 4);   // (w7,w8)
    float am, a0, b1, b2, c3, c4, d5, d6, e7, e8;
    upk(PA, am, a0); upk(PB, b1, b2); upk(PC, c3, c4);
    upk(PD, d5, d6); upk(PE, e7, e8);
    const u64 S1 = add2(PB, PD);                  // (w1+w5, w2+w6)
    const u64 S2 = pk(b2 + c4, c3 + d5);          // (w2+w4, w3+w5)
    const u64 T1 = pk(a0 + d6, b1 + e7);          // (w0+w6, w1+w7)
    loxy = fma2(S1, g0p, fma2(S2, g1p, mul2(PC, g2p)));
    hizw = fma2(T1, h0p, fma2(S1, h1p, fma2(S2, h2p, mul2(PC, h3p))));
}

__global__ __launch_bounds__(NTHREADS, 4) void scat_kernel(
    const float* __restrict__ x,
    float* __restrict__ out)
{
    extern __shared__ float smem[];        // [NWARP][NSLOT][SEGW]

    const int tid  = threadIdx.x;
    const int wi   = tid >> 5;             // warp 0..7
    const int lane = tid & 31;
    const int img  = blockIdx.z;
    const int OY0  = blockIdx.y * TILE_OY;
    const float* __restrict__ xin = x + (size_t)img * (512*512);
    float* seg = smem + wi * (NSLOT*SEGW); // this warp's private ring

    const int b_  = img / 3;
    const int ch_ = img % 3;
    const int c   = 32*wi + lane;          // global pair-column (output x)
    float* o = out + (((size_t)b_*21 + ch_)*256 + OY0)*256 + c;
    const size_t cs = (size_t)3*256*256;

    const u64 g0p = pk(G0, G0), g1p = pk(G1, G1), g2p = pk(G2, G2);
    const u64 h0p = pk(H0, H0), h1p = pk(H1, H1), h2p = pk(H2, H2), h3p = pk(H3, H3);

    const int R = 2*OY0 - 3;               // input row = R + m, m = 0..37
    const int cofs = 8 + 2*lane;           // float offset of center pair in a segment

    // ---- prologue: stage rows m=0..13, ring-fill m=0..5 (warp-local only) ----
    stage_rows(xin, seg, lane, wi, R, 0, 14);
    commit_group();
    wait_all();
    __syncwarp();

    u64 rxy[8], rzw[8];
    #pragma unroll
    for (int j = 0; j < 6; j++)
        hfilt_row(seg + j*SEGW + cofs, g0p, g1p, g2p, h0p, h1p, h2p, h3p,
                  rxy[j], rzw[j]);

    #pragma unroll 1
    for (int i = 0; i < 4; ++i) {          // 4 output rows per iteration
        if (i > 0) {                       // rows 6+8i..13+8i (staged at iter i-1) landed
            wait_all();
            __syncwarp();
        }
        if (i < 3)  {                      // stage rows for iter i+1
            stage_rows(xin, seg, lane, wi, R, 14 + 8*i, 8);
            commit_group();
        }

        #pragma unroll
        for (int u = 0; u < 4; ++u) {
            const int m6 = 8*i + 6 + 2*u;  // two new rows completing window m..m+7
            hfilt_row(seg + ((m6    ) & (NSLOT-1))*SEGW + cofs,
                      g0p, g1p, g2p, h0p, h1p, h2p, h3p,
                      rxy[(6 + 2*u) & 7], rzw[(6 + 2*u) & 7]);
            hfilt_row(seg + ((m6 + 1) & (NSLOT-1))*SEGW + cofs,
                      g0p, g1p, g2p, h0p, h1p, h2p, h3p,
                      rxy[(7 + 2*u) & 7], rzw[(7 + 2*u) & 7]);

            const int w0 = 2*u;            // compile-time window base

            float llp, m15, m165, m45, m135, m75, m105;
            #pragma unroll
            for (int plane = 0; plane < 2; plane++) {
                const u64* r = plane ? rzw : rxy;
                const u64 r0 = r[(w0 + 0) & 7], r1 = r[(w0 + 1) & 7];
                const u64 r2 = r[(w0 + 2) & 7], r3 = r[(w0 + 3) & 7];
                const u64 r4 = r[(w0 + 4) & 7], r5 = r[(w0 + 5) & 7];
                const u64 r6 = r[(w0 + 6) & 7], r7 = r[(w0 + 7) & 7];

                const u64 A06 = add2(r0, r6), A15 = add2(r1, r5), A24 = add2(r2, r4);
                const u64 A17 = add2(r1, r7), A26 = add2(r2, r6), A35 = add2(r3, r5);

                const u64 F0 = fma2(A06, h0p, fma2(A15, h1p, fma2(A24, h2p, mul2(r3, h3p))));
                const u64 F1 = fma2(A17, h0p, fma2(A26, h1p, fma2(A35, h2p, mul2(r4, h3p))));

                float f0x, f0y, f1x, f1y;
                upk(F0, f0x, f0y); upk(F1, f1x, f1y);

                if (plane == 0) {
                    m15  = bandmag(f0x - f1y, f0y + f1x);
                    m165 = bandmag(f0x + f1y, f0y - f1x);
                    // pooled LL: summed 5-tap filter applied once
                    const u64 B  = add2(A15, A26);
                    const u64 Cs = add2(A24, A35);
                    const u64 Ds = add2(r3, r4);
                    const u64 LLs = fma2(B, g0p, fma2(Cs, g1p, mul2(Ds, g2p)));
                    float s0, s1;
                    upk(LLs, s0, s1);
                    llp = 0.25f * (s0 + s1);
                } else {
                    m45  = bandmag(f0x - f1y, f0y + f1x);
                    m135 = bandmag(f0x + f1y, f0y - f1x);
                    const u64 E0 = fma2(A15, g0p, fma2(A24, g1p, mul2(r3, g2p)));
                    const u64 E1 = fma2(A26, g0p, fma2(A35, g1p, mul2(r4, g2p)));
                    float e0x, e0y, e1x, e1y;
                    upk(E0, e0x, e0y); upk(E1, e1x, e1y);
                    m75  = bandmag(e0x - e1y, e0y + e1x);
                    m105 = bandmag(e0x + e1y, e0y - e1x);
                }
            }

            o[0]    = llp;
            o[1*cs] = m15;
            o[2*cs] = m45;
            o[3*cs] = m75;
            o[4*cs] = m105;
            o[5*cs] = m135;
            o[6*cs] = m165;
            o += 256;                      // next output row
        }
    }
}

extern "C" void kernel_launch(void* const* d_in, const int* in_sizes, int n_in,
                              void* d_out, int out_size) {
    const float* x = (const float*)d_in[0];
    float* out = (float*)d_out;

    cudaFuncSetAttribute(scat_kernel,
                         cudaFuncAttributeMaxDynamicSharedMemorySize, SMEM_BYTES);

    dim3 grid(1, 256/TILE_OY, 96);         // (1, 16, 96)
    scat_kernel<<<grid, NTHREADS, SMEM_BYTES>>>(x, out);
}